// round 13
// baseline (speedup 1.0000x reference)
#include <cuda_runtime.h>
#include <math.h>

#define SEQ   2048
#define HDIM  1024
#define GDIM  4096   // 4*H
#define NCLS  512
#define NB    128    // scan CTAs (<= SM count -> all resident)
#define NHELP 20     // helper GEMM CTAs (idle SMs during scan)
#define NGRP  8      // warp-group arrival counters

typedef unsigned long long ull;

// ---------------- scratch (static device globals) ------------------------------
__device__ float    g_gxA[SEQ * GDIM];     // 32 MB: gate buffer A (layers 0,2)
__device__ float    g_gxB[SEQ * GDIM];     // 32 MB: gate buffer B (layer 1)
__device__ float    g_seqA[SEQ * HDIM];    // 8 MB: layer output ping
__device__ float    g_seqB[SEQ * HDIM];    // 8 MB: layer output pong
__device__ float    g_Wt0[HDIM * GDIM];    // 16 MB: W_ih_0^T
__device__ float    g_Wt1[HDIM * GDIM];    // 16 MB: W_ih_1^T
__device__ float    g_Wt2[HDIM * GDIM];    // 16 MB: W_ih_2^T
__device__ float    g_Wt3[HDIM * NCLS];    // 2 MB: fc_w^T
__device__ float    g_bzero[GDIM];         // stays zero (dummy 2nd bias)
__device__ unsigned g_cnt[NGRP * SEQ];     // cnt[g*SEQ + t]

// ---------------- packed f32x2 helpers (no volatile) ----------------------------
__device__ __forceinline__ ull pk(float lo, float hi) {
    ull r; asm("mov.b64 %0, {%1, %2};" : "=l"(r) : "f"(lo), "f"(hi)); return r;
}
__device__ __forceinline__ float2 up(ull v) {
    float2 r; asm("mov.b64 {%0, %1}, %2;" : "=f"(r.x), "=f"(r.y) : "l"(v)); return r;
}
__device__ __forceinline__ void fma2(ull& d, ull a, ull b) {
    asm("fma.rn.f32x2 %0, %1, %2, %0;" : "+l"(d) : "l"(a), "l"(b));
}

// ---------------- fast, overflow-safe activations (validated) -------------------
__device__ __forceinline__ float fast_sigmoid(float x) {
    return __fdividef(1.f, 1.f + __expf(-x));
}
__device__ __forceinline__ float fast_tanh(float x) {
    float ax = fabsf(x);
    float e  = __expf(2.f * ax);
    float t  = 1.f - __fdividef(2.f, e + 1.f);
    return copysignf(t, x);
}

// ---------------- transpose: Wt[c][r] = W[r][c] ----------------------------------
__global__ void transpose_k(const float* __restrict__ W, float* __restrict__ Wt,
                            int R, int C) {
    __shared__ float tile[32][33];
    int c0 = blockIdx.x * 32, r0 = blockIdx.y * 32;
    int x = threadIdx.x, y = threadIdx.y;
#pragma unroll
    for (int j = 0; j < 32; j += 8)
        tile[y + j][x] = W[(size_t)(r0 + y + j) * C + (c0 + x)];
    __syncthreads();
#pragma unroll
    for (int j = 0; j < 32; j += 8)
        Wt[(size_t)(c0 + y + j) * R + (r0 + x)] = tile[x][y + j];
}

// ---------------- zero counters ----------------------------------------------------
__global__ void zero_k(unsigned* p, int n) {
    int i = blockIdx.x * 256 + threadIdx.x;
    if (i < n) p[i] = 0;
}

// ---------------- standalone SGEMM (r12, full-chip, for layer-0 gx) -----------------
__global__ void __launch_bounds__(256, 2) sgemm_bias_k(
    const float* __restrict__ A, const float* __restrict__ B,
    const float* __restrict__ b1, const float* __restrict__ b2,
    float* __restrict__ C, int M, int N, int K) {
    __shared__ float As[2][16][128];
    __shared__ float Bs[2][16][128];
    const int tid  = threadIdx.x;
    const int tx   = tid & 15;
    const int ty   = tid >> 4;
    const int brow = blockIdx.y * 128;
    const int bcol = blockIdx.x * 128;

    const int arow = tid >> 1;
    const int ak   = (tid & 1) * 8;
    const int bk   = tid >> 4;
    const int bn   = (tid & 15) * 4;

    const float* Aptr = A + (size_t)(brow + arow) * K + ak;
    const float* Bptr = B + (size_t)bk * N + bcol + bn;

    ull acc2[8][4];
#pragma unroll
    for (int i = 0; i < 8; i++)
#pragma unroll
        for (int j = 0; j < 4; j++) acc2[i][j] = 0ull;

    float4 av0 = *(const float4*)(Aptr);
    float4 av1 = *(const float4*)(Aptr + 4);
    float4 bv0 = *(const float4*)(Bptr);
    float4 bv1 = *(const float4*)(Bptr + 64);
    As[0][ak + 0][arow] = av0.x; As[0][ak + 1][arow] = av0.y;
    As[0][ak + 2][arow] = av0.z; As[0][ak + 3][arow] = av0.w;
    As[0][ak + 4][arow] = av1.x; As[0][ak + 5][arow] = av1.y;
    As[0][ak + 6][arow] = av1.z; As[0][ak + 7][arow] = av1.w;
    *(float4*)&Bs[0][bk][bn]      = bv0;
    *(float4*)&Bs[0][bk][bn + 64] = bv1;

    int cur = 0;
    for (int k0 = 0; k0 < K; k0 += 16) {
        __syncthreads();
        const bool more = (k0 + 16) < K;
        if (more) {
            av0 = *(const float4*)(Aptr + k0 + 16);
            av1 = *(const float4*)(Aptr + k0 + 20);
            bv0 = *(const float4*)(Bptr + (size_t)(k0 + 16) * N);
            bv1 = *(const float4*)(Bptr + (size_t)(k0 + 16) * N + 64);
        }
#pragma unroll
        for (int kk = 0; kk < 16; kk++) {
            float a[8];
            *(float4*)&a[0] = *(const float4*)&As[cur][kk][ty * 4];
            *(float4*)&a[4] = *(const float4*)&As[cur][kk][64 + ty * 4];
            float4 bq0 = *(const float4*)&Bs[cur][kk][tx * 4];
            float4 bq1 = *(const float4*)&Bs[cur][kk][64 + tx * 4];
            ull b01 = pk(bq0.x, bq0.y);
            ull b23 = pk(bq0.z, bq0.w);
            ull b45 = pk(bq1.x, bq1.y);
            ull b67 = pk(bq1.z, bq1.w);
#pragma unroll
            for (int i = 0; i < 8; i++) {
                ull sa = pk(a[i], a[i]);
                fma2(acc2[i][0], sa, b01);
                fma2(acc2[i][1], sa, b23);
                fma2(acc2[i][2], sa, b45);
                fma2(acc2[i][3], sa, b67);
            }
        }
        if (more) {
            const int nxt = cur ^ 1;
            As[nxt][ak + 0][arow] = av0.x; As[nxt][ak + 1][arow] = av0.y;
            As[nxt][ak + 2][arow] = av0.z; As[nxt][ak + 3][arow] = av0.w;
            As[nxt][ak + 4][arow] = av1.x; As[nxt][ak + 5][arow] = av1.y;
            As[nxt][ak + 6][arow] = av1.z; As[nxt][ak + 7][arow] = av1.w;
            *(float4*)&Bs[nxt][bk][bn]      = bv0;
            *(float4*)&Bs[nxt][bk][bn + 64] = bv1;
            cur = nxt;
        }
    }
#pragma unroll
    for (int i = 0; i < 8; i++) {
        int row = brow + ((i < 4) ? (ty * 4 + i) : (64 + ty * 4 + (i - 4)));
#pragma unroll
        for (int jq = 0; jq < 2; jq++) {
            int col = bcol + ((jq == 0) ? (tx * 4) : (64 + tx * 4));
            float2 lo = up(acc2[i][jq * 2 + 0]);
            float2 hi = up(acc2[i][jq * 2 + 1]);
            float4 o;
            o.x = lo.x + b1[col + 0] + b2[col + 0];
            o.y = lo.y + b1[col + 1] + b2[col + 1];
            o.z = hi.x + b1[col + 2] + b2[col + 2];
            o.w = hi.y + b1[col + 3] + b2[col + 3];
            *(float4*)&C[(size_t)row * N + col] = o;
        }
    }
}

// ---------------- fused scan + helper GEMM ------------------------------------------
// Grid = 148 (all wave-1 resident). CTAs 0..127: r12-champion scan, unchanged.
// CTAs 128..147: next-layer gx GEMM (or FC head), tile (r,c); tile waits on
// cnt[g][128r+127]==NB (acquire) so A rows [128r,128r+128) of seqout are final.
// Helpers never block the scan (one-way dependency -> deadlock-free).
__global__ void __launch_bounds__(256, 1) scan_fused_k(
    const float* __restrict__ Whh, const float* __restrict__ gx,
    float* __restrict__ seqout, unsigned* __restrict__ cnt,
    const float* __restrict__ gB, const float* __restrict__ gb1,
    const float* __restrict__ gb2, float* __restrict__ gC, int gN) {
    __shared__ __align__(16) float smem[8192];   // 32KB: scan uses 4KB, helper all
    const int tid = threadIdx.x;

    if (blockIdx.x < NB) {
        // ================= scan (r12 champion, verbatim) =================
        float4* sh = (float4*)smem;
        const int lane = tid & 31;
        const int w    = tid >> 5;
        const int u    = blockIdx.x * 8 + w;

        float4 wr[4][8];
#pragma unroll
        for (int g = 0; g < 4; g++) {
            const float* wp = Whh + (size_t)(g * HDIM + u) * HDIM + lane * 4;
#pragma unroll
            for (int c = 0; c < 8; c++) wr[g][c] = *(const float4*)(wp + c * 128);
        }

        float cst = 0.f;
        const float4* hsrc = 0;

        for (int t = 0; t < SEQ; t++) {
            const float* p = gx + (size_t)t * GDIM + u;
            float gi = __ldg(p);
            float gf = __ldg(p + HDIM);
            float gg = __ldg(p + 2 * HDIM);
            float go = __ldg(p + 3 * HDIM);

            if (t == 0) {
                sh[tid] = make_float4(0.f, 0.f, 0.f, 0.f);
                __syncthreads();
            } else {
                if (w == 0) {
                    if (lane < NGRP) {
                        const unsigned* cp = cnt + lane * SEQ + (t - 1);
                        unsigned v;
                        do {
                            asm volatile("ld.acquire.gpu.global.u32 %0, [%1];"
                                         : "=r"(v) : "l"(cp) : "memory");
                        } while (v < (unsigned)NB);
                    }
                    __syncwarp();
                }
                __syncthreads();
                sh[tid] = __ldcg(hsrc + tid);
                __syncthreads();
            }

            float a0 = 0.f, a1 = 0.f, a2 = 0.f, a3 = 0.f;
#pragma unroll
            for (int c = 0; c < 8; c++) {
                float4 hv = sh[c * 32 + lane];
                a0 = fmaf(wr[0][c].x, hv.x, a0); a0 = fmaf(wr[0][c].y, hv.y, a0);
                a0 = fmaf(wr[0][c].z, hv.z, a0); a0 = fmaf(wr[0][c].w, hv.w, a0);
                a1 = fmaf(wr[1][c].x, hv.x, a1); a1 = fmaf(wr[1][c].y, hv.y, a1);
                a1 = fmaf(wr[1][c].z, hv.z, a1); a1 = fmaf(wr[1][c].w, hv.w, a1);
                a2 = fmaf(wr[2][c].x, hv.x, a2); a2 = fmaf(wr[2][c].y, hv.y, a2);
                a2 = fmaf(wr[2][c].z, hv.z, a2); a2 = fmaf(wr[2][c].w, hv.w, a2);
                a3 = fmaf(wr[3][c].x, hv.x, a3); a3 = fmaf(wr[3][c].y, hv.y, a3);
                a3 = fmaf(wr[3][c].z, hv.z, a3); a3 = fmaf(wr[3][c].w, hv.w, a3);
            }
#pragma unroll
            for (int s = 16; s > 0; s >>= 1) {
                a0 += __shfl_xor_sync(0xffffffffu, a0, s);
                a1 += __shfl_xor_sync(0xffffffffu, a1, s);
                a2 += __shfl_xor_sync(0xffffffffu, a2, s);
                a3 += __shfl_xor_sync(0xffffffffu, a3, s);
            }
            float iv = fast_sigmoid(a0 + gi);
            float fv = fast_sigmoid(a1 + gf);
            float gv = fast_tanh(a2 + gg);
            float ov = fast_sigmoid(a3 + go);
            cst = fmaf(fv, cst, iv * gv);
            float h = ov * fast_tanh(cst);

            if (lane == 0) {
                seqout[(size_t)t * HDIM + u] = h;
                asm volatile("red.release.gpu.global.add.u32 [%0], 1;"
                             :: "l"(cnt + w * SEQ + t) : "memory");
            }
            hsrc = (const float4*)(seqout + (size_t)t * HDIM);
        }
    } else {
        // ================= helper GEMM: gC = seqout @ gB + gb1 + gb2 =====
        float (*As)[16][128] = (float(*)[16][128])(smem);
        float (*Bs)[16][128] = (float(*)[16][128])(smem + 4096);
        const int hid = blockIdx.x - NB;
        const int tiles_n = gN >> 7;
        const int ntiles  = (SEQ / 128) * tiles_n;
        const int tx   = tid & 15;
        const int ty   = tid >> 4;
        const int arow = tid >> 1;
        const int ak   = (tid & 1) * 8;
        const int bk   = tid >> 4;
        const int bn   = (tid & 15) * 4;

        for (int idx = hid; idx < ntiles; idx += NHELP) {
            const int r = idx / tiles_n;
            const int c = idx - r * tiles_n;
            // gate: scan must have finished step 128r+127 (A rows final)
            if (tid < NGRP) {
                const unsigned* cp = cnt + tid * SEQ + (r * 128 + 127);
                unsigned v;
                do {
                    asm volatile("ld.acquire.gpu.global.u32 %0, [%1];"
                                 : "=r"(v) : "l"(cp) : "memory");
                } while (v < (unsigned)NB);
            }
            __syncthreads();   // also fences smem reuse across tiles

            const int brow = r * 128;
            const int bcol = c * 128;
            const float* Aptr = seqout + (size_t)(brow + arow) * HDIM + ak;
            const float* Bptr = gB + (size_t)bk * gN + bcol + bn;

            ull acc2[8][4];
#pragma unroll
            for (int i = 0; i < 8; i++)
#pragma unroll
                for (int j = 0; j < 4; j++) acc2[i][j] = 0ull;

            float4 av0 = *(const float4*)(Aptr);
            float4 av1 = *(const float4*)(Aptr + 4);
            float4 bv0 = *(const float4*)(Bptr);
            float4 bv1 = *(const float4*)(Bptr + 64);
            As[0][ak + 0][arow] = av0.x; As[0][ak + 1][arow] = av0.y;
            As[0][ak + 2][arow] = av0.z; As[0][ak + 3][arow] = av0.w;
            As[0][ak + 4][arow] = av1.x; As[0][ak + 5][arow] = av1.y;
            As[0][ak + 6][arow] = av1.z; As[0][ak + 7][arow] = av1.w;
            *(float4*)&Bs[0][bk][bn]      = bv0;
            *(float4*)&Bs[0][bk][bn + 64] = bv1;

            int cur = 0;
            for (int k0 = 0; k0 < HDIM; k0 += 16) {
                __syncthreads();
                const bool more = (k0 + 16) < HDIM;
                if (more) {
                    av0 = *(const float4*)(Aptr + k0 + 16);
                    av1 = *(const float4*)(Aptr + k0 + 20);
                    bv0 = *(const float4*)(Bptr + (size_t)(k0 + 16) * gN);
                    bv1 = *(const float4*)(Bptr + (size_t)(k0 + 16) * gN + 64);
                }
#pragma unroll
                for (int kk = 0; kk < 16; kk++) {
                    float a[8];
                    *(float4*)&a[0] = *(const float4*)&As[cur][kk][ty * 4];
                    *(float4*)&a[4] = *(const float4*)&As[cur][kk][64 + ty * 4];
                    float4 bq0 = *(const float4*)&Bs[cur][kk][tx * 4];
                    float4 bq1 = *(const float4*)&Bs[cur][kk][64 + tx * 4];
                    ull b01 = pk(bq0.x, bq0.y);
                    ull b23 = pk(bq0.z, bq0.w);
                    ull b45 = pk(bq1.x, bq1.y);
                    ull b67 = pk(bq1.z, bq1.w);
#pragma unroll
                    for (int i = 0; i < 8; i++) {
                        ull sa = pk(a[i], a[i]);
                        fma2(acc2[i][0], sa, b01);
                        fma2(acc2[i][1], sa, b23);
                        fma2(acc2[i][2], sa, b45);
                        fma2(acc2[i][3], sa, b67);
                    }
                }
                if (more) {
                    const int nxt = cur ^ 1;
                    As[nxt][ak + 0][arow] = av0.x; As[nxt][ak + 1][arow] = av0.y;
                    As[nxt][ak + 2][arow] = av0.z; As[nxt][ak + 3][arow] = av0.w;
                    As[nxt][ak + 4][arow] = av1.x; As[nxt][ak + 5][arow] = av1.y;
                    As[nxt][ak + 6][arow] = av1.z; As[nxt][ak + 7][arow] = av1.w;
                    *(float4*)&Bs[nxt][bk][bn]      = bv0;
                    *(float4*)&Bs[nxt][bk][bn + 64] = bv1;
                    cur = nxt;
                }
            }
#pragma unroll
            for (int i = 0; i < 8; i++) {
                int row = brow + ((i < 4) ? (ty * 4 + i) : (64 + ty * 4 + (i - 4)));
#pragma unroll
                for (int jq = 0; jq < 2; jq++) {
                    int col = bcol + ((jq == 0) ? (tx * 4) : (64 + tx * 4));
                    float2 lo = up(acc2[i][jq * 2 + 0]);
                    float2 hi = up(acc2[i][jq * 2 + 1]);
                    float4 o;
                    o.x = lo.x + gb1[col + 0] + gb2[col + 0];
                    o.y = lo.y + gb1[col + 1] + gb2[col + 1];
                    o.z = hi.x + gb1[col + 2] + gb2[col + 2];
                    o.w = hi.y + gb1[col + 3] + gb2[col + 3];
                    *(float4*)&gC[(size_t)row * gN + col] = o;
                }
            }
        }
    }
}

// ---------------- launch ----------------
extern "C" void kernel_launch(void* const* d_in, const int* in_sizes, int n_in,
                              void* d_out, int out_size) {
    const float* x      = (const float*)d_in[0];
    const float* Wih[3] = {(const float*)d_in[1], (const float*)d_in[5],  (const float*)d_in[9]};
    const float* Whh[3] = {(const float*)d_in[2], (const float*)d_in[6],  (const float*)d_in[10]};
    const float* bih[3] = {(const float*)d_in[3], (const float*)d_in[7],  (const float*)d_in[11]};
    const float* bhh[3] = {(const float*)d_in[4], (const float*)d_in[8],  (const float*)d_in[12]};
    const float* fcw    = (const float*)d_in[13];
    const float* fcb    = (const float*)d_in[14];
    float* out = (float*)d_out;

    float *gxA, *gxB, *seqA, *seqB, *Wt0, *Wt1, *Wt2, *Wt3, *bz;
    unsigned* cnt;
    cudaGetSymbolAddress((void**)&gxA,  g_gxA);
    cudaGetSymbolAddress((void**)&gxB,  g_gxB);
    cudaGetSymbolAddress((void**)&seqA, g_seqA);
    cudaGetSymbolAddress((void**)&seqB, g_seqB);
    cudaGetSymbolAddress((void**)&Wt0,  g_Wt0);
    cudaGetSymbolAddress((void**)&Wt1,  g_Wt1);
    cudaGetSymbolAddress((void**)&Wt2,  g_Wt2);
    cudaGetSymbolAddress((void**)&Wt3,  g_Wt3);
    cudaGetSymbolAddress((void**)&bz,   g_bzero);
    cudaGetSymbolAddress((void**)&cnt,  g_cnt);

    dim3 tb(32, 8);
    // all transposes upfront
    transpose_k<<<dim3(HDIM / 32, GDIM / 32), tb>>>(Wih[0], Wt0, GDIM, HDIM);
    transpose_k<<<dim3(HDIM / 32, GDIM / 32), tb>>>(Wih[1], Wt1, GDIM, HDIM);
    transpose_k<<<dim3(HDIM / 32, GDIM / 32), tb>>>(Wih[2], Wt2, GDIM, HDIM);
    transpose_k<<<dim3(HDIM / 32, NCLS / 32), tb>>>(fcw,    Wt3, NCLS, HDIM);

    // layer-0 gx: full-chip GEMM (no dependency to hide it under)
    sgemm_bias_k<<<dim3(GDIM / 128, SEQ / 128), 256>>>(
        x, Wt0, bih[0], bhh[0], gxA, SEQ, GDIM, HDIM);

    // layer 0 scan + hidden GEMM for layer-1 gx (seqA -> gxB)
    zero_k<<<(NGRP * SEQ + 255) / 256, 256>>>(cnt, NGRP * SEQ);
    scan_fused_k<<<NB + NHELP, 256>>>(Whh[0], gxA, seqA, cnt,
                                      Wt1, bih[1], bhh[1], gxB, GDIM);
    // layer 1 scan + hidden GEMM for layer-2 gx (seqB -> gxA)
    zero_k<<<(NGRP * SEQ + 255) / 256, 256>>>(cnt, NGRP * SEQ);
    scan_fused_k<<<NB + NHELP, 256>>>(Whh[1], gxB, seqB, cnt,
                                      Wt2, bih[2], bhh[2], gxA, GDIM);
    // layer 2 scan + hidden FC head (seqA -> out)
    zero_k<<<(NGRP * SEQ + 255) / 256, 256>>>(cnt, NGRP * SEQ);
    scan_fused_k<<<NB + NHELP, 256>>>(Whh[2], gxA, seqA, cnt,
                                      Wt3, fcb, bz, out, NCLS);
}